// round 1
// baseline (speedup 1.0000x reference)
#include <cuda_runtime.h>
#include <cuda_bf16.h>
#include <math.h>

#define T_   16384
#define C_   1024
#define H_   16
#define D_   64
#define P_   512
#define L_   1024
#define HID_ 4096
#define NM_  9216

__device__ float g_m[NM_];
__device__ float g_h[(size_t)T_ * C_];
__device__ float g_q[(size_t)T_ * C_];
__device__ float g_o[(size_t)T_ * C_];
__device__ float g_x[(size_t)T_ * C_];
__device__ float g_S[(size_t)H_ * T_ * P_];
__device__ float g_hp[(size_t)P_ * C_];
__device__ float g_kv[(size_t)P_ * 2 * C_];
__device__ float g_xp0[(size_t)P_ * C_];
__device__ float g_xp[(size_t)P_ * C_];
__device__ float g_hp2[(size_t)P_ * C_];
__device__ float g_cq[(size_t)P_ * C_];
__device__ float g_ckv[(size_t)L_ * 2 * C_];
__device__ float g_S2[(size_t)H_ * P_ * L_];
__device__ float g_co[(size_t)P_ * C_];
__device__ float g_ab[(size_t)P_ * 2 * HID_];
__device__ float g_gact[(size_t)P_ * HID_];
__device__ int   g_cnt[P_];
__device__ int   g_members[P_ * 64];

template<bool BT, int EPI>
__global__ __launch_bounds__(256)
void gemm_kernel(int M, int N, int K,
                 const float* __restrict__ A, int lda, long aB,
                 const float* __restrict__ B, int bKs, int bNs, long bB,
                 float* __restrict__ Cp, int ldc, long cB,
                 const float* __restrict__ bias,
                 const float* __restrict__ resid, int ldr,
                 const float* __restrict__ gate)
{
    const int BM = 128, BN = 128, BK = 8;
    __shared__ float As[BK][BM + 8];
    __shared__ float Bs[BK][BN + 8];
    int bz = blockIdx.z;
    const float* Ab = A + (long)bz * aB;
    const float* Bb = B + (long)bz * bB;
    float*       Cb = Cp + (long)bz * cB;
    int row0 = blockIdx.y * BM;
    int col0 = blockIdx.x * BN;
    int tid = threadIdx.x;
    int tx = tid & 15, ty = tid >> 4;

    float acc[8][8];
#pragma unroll
    for (int i = 0; i < 8; i++)
#pragma unroll
        for (int j = 0; j < 8; j++) acc[i][j] = 0.f;

    for (int k0 = 0; k0 < K; k0 += BK) {
#pragma unroll
        for (int i = 0; i < 4; i++) {
            int idx = tid + i * 256;
            int m = idx >> 3, kk = idx & 7;
            int gm = row0 + m;
            As[kk][m] = (gm < M) ? Ab[(long)gm * lda + (k0 + kk)] : 0.f;
        }
        if (BT) {
#pragma unroll
            for (int i = 0; i < 4; i++) {
                int idx = tid + i * 256;
                int n = idx >> 3, kk = idx & 7;
                int gn = col0 + n;
                Bs[kk][n] = (gn < N) ? Bb[(long)(k0 + kk) * bKs + (long)gn * bNs] : 0.f;
            }
        } else {
#pragma unroll
            for (int i = 0; i < 4; i++) {
                int idx = tid + i * 256;
                int kk = idx >> 7, n = idx & 127;
                int gn = col0 + n;
                Bs[kk][n] = (gn < N) ? Bb[(long)(k0 + kk) * bKs + (long)gn * bNs] : 0.f;
            }
        }
        __syncthreads();
#pragma unroll
        for (int kk = 0; kk < BK; kk++) {
            float a[8], b[8];
#pragma unroll
            for (int i = 0; i < 8; i++) a[i] = As[kk][ty * 8 + i];
#pragma unroll
            for (int j = 0; j < 8; j++) b[j] = Bs[kk][tx * 8 + j];
#pragma unroll
            for (int i = 0; i < 8; i++)
#pragma unroll
                for (int j = 0; j < 8; j++) acc[i][j] += a[i] * b[j];
        }
        __syncthreads();
    }

#pragma unroll
    for (int i = 0; i < 8; i++) {
        int gm = row0 + ty * 8 + i;
        if (gm >= M) continue;
#pragma unroll
        for (int j = 0; j < 8; j++) {
            int gn = col0 + tx * 8 + j;
            if (gn >= N) continue;
            float v = acc[i][j];
            if (bias) v += bias[gn];
            if (EPI == 1) v = resid[(long)gm * ldr + gn] + v * gate[gn];
            Cb[(long)gm * ldc + gn] = v;
        }
    }
}

__global__ void modproj_kernel(const float* __restrict__ mod,
                               const float* __restrict__ Wm,
                               const float* __restrict__ bm)
{
    __shared__ float sm[C_];
    for (int i = threadIdx.x; i < C_; i += blockDim.x) {
        float v = mod[i];
        sm[i] = v / (1.f + expf(-v));
    }
    __syncthreads();
    int j = blockIdx.x * blockDim.x + threadIdx.x;
    if (j < NM_) {
        float acc = bm[j];
        for (int i = 0; i < C_; i++) acc += sm[i] * Wm[(long)i * NM_ + j];
        g_m[j] = acc;
    }
}

__global__ void ln_mod_kernel(const float* __restrict__ in, float* __restrict__ out,
                              const float* __restrict__ sc, const float* __restrict__ sh)
{
    __shared__ float rs[256], rs2[256];
    int r = blockIdx.x, tid = threadIdx.x;
    const float* x = in + (long)r * C_;
    float v[4], s = 0.f, s2 = 0.f;
#pragma unroll
    for (int i = 0; i < 4; i++) { v[i] = x[tid + i * 256]; s += v[i]; s2 += v[i] * v[i]; }
    rs[tid] = s; rs2[tid] = s2; __syncthreads();
    for (int o = 128; o; o >>= 1) {
        if (tid < o) { rs[tid] += rs[tid + o]; rs2[tid] += rs2[tid + o]; }
        __syncthreads();
    }
    float mu = rs[0] * (1.f / C_);
    float var = rs2[0] * (1.f / C_) - mu * mu;
    float rstd = rsqrtf(fmaxf(var, 0.f) + 1e-6f);
#pragma unroll
    for (int i = 0; i < 4; i++) {
        int c = tid + i * 256;
        out[(long)r * C_ + c] = (v[i] - mu) * rstd * (1.f + sc[c]) + sh[c];
    }
}

__global__ void build_members_kernel(const int* __restrict__ inv)
{
    int t = blockIdx.x * blockDim.x + threadIdx.x;
    if (t < T_) {
        int p = inv[t];
        int s = atomicAdd(&g_cnt[p], 1);
        if (s < 64) g_members[p * 64 + s] = t;
    }
}

__global__ void sort_members_kernel()
{
    int p = blockIdx.x * blockDim.x + threadIdx.x;
    if (p < P_) {
        int n = min(g_cnt[p], 64);
        int* a = &g_members[p * 64];
        for (int i = 1; i < n; i++) {
            int key = a[i], j = i - 1;
            while (j >= 0 && a[j] > key) { a[j + 1] = a[j]; --j; }
            a[j + 1] = key;
        }
    }
}

__global__ void seg_mean_kernel(const float* __restrict__ in, float* __restrict__ out,
                                float* __restrict__ out2)
{
    int p = blockIdx.x, tid = threadIdx.x;
    int n = min(g_cnt[p], 64);
    float acc[4] = {0.f, 0.f, 0.f, 0.f};
    for (int j = 0; j < n; j++) {
        long base = (long)g_members[p * 64 + j] * C_;
#pragma unroll
        for (int i = 0; i < 4; i++) acc[i] += in[base + tid + i * 256];
    }
    float invn = n ? 1.f / n : 0.f;
#pragma unroll
    for (int i = 0; i < 4; i++) {
        float val = acc[i] * invn;
        out[(long)p * C_ + tid + i * 256] = val;
        if (out2) out2[(long)p * C_ + tid + i * 256] = val;
    }
}

__global__ void rope_norm_kernel(float* __restrict__ x, int rowStride, int rows,
                                 const int* __restrict__ coords, int cmult,
                                 const float* __restrict__ gamma)
{
    long gw = ((long)blockIdx.x * blockDim.x + threadIdx.x) >> 5;
    if (gw >= (long)rows * H_) return;
    int lane = threadIdx.x & 31;
    int t = (int)(gw / H_), h = (int)(gw % H_);
    float* base = x + (long)t * rowStride + h * D_;
    float x0 = base[2 * lane], x1 = base[2 * lane + 1];
    float c = 1.f, s = 0.f;
    if (lane < 30) {
        int a = lane / 10, f = lane % 10;
        float freq = powf(10000.f, -(float)f * 0.1f);
        float ang = (float)(coords[t * 3 + a] * cmult) * freq;
        c = cosf(ang); s = sinf(ang);
    }
    float re = x0 * c - x1 * s;
    float im = x0 * s + x1 * c;
    float ss = re * re + im * im;
#pragma unroll
    for (int o = 16; o; o >>= 1) ss += __shfl_xor_sync(0xffffffffu, ss, o);
    float nrm = sqrtf(ss);
    float scl = 8.f / fmaxf(nrm, 1e-12f);
    base[2 * lane]     = re * scl * gamma[h * D_ + 2 * lane];
    base[2 * lane + 1] = im * scl * gamma[h * D_ + 2 * lane + 1];
}

template<int PER>
__global__ void softmax_kernel(float* __restrict__ S, long rows, float scale)
{
    long gw = ((long)blockIdx.x * blockDim.x + threadIdx.x) >> 5;
    if (gw >= rows) return;
    int lane = threadIdx.x & 31;
    float* row = S + gw * (PER * 32);
    float v[PER], mx = -1e30f;
#pragma unroll
    for (int i = 0; i < PER; i++) { v[i] = row[lane + i * 32] * scale; mx = fmaxf(mx, v[i]); }
#pragma unroll
    for (int o = 16; o; o >>= 1) mx = fmaxf(mx, __shfl_xor_sync(0xffffffffu, mx, o));
    float s = 0.f;
#pragma unroll
    for (int i = 0; i < PER; i++) { v[i] = expf(v[i] - mx); s += v[i]; }
#pragma unroll
    for (int o = 16; o; o >>= 1) s += __shfl_xor_sync(0xffffffffu, s, o);
    float inv = 1.f / s;
#pragma unroll
    for (int i = 0; i < PER; i++) row[lane + i * 32] = v[i] * inv;
}

__global__ void silugate_kernel()
{
    long idx = (long)blockIdx.x * blockDim.x + threadIdx.x;
    if (idx < (long)P_ * HID_) {
        int p = (int)(idx >> 12), i = (int)(idx & (HID_ - 1));
        float a = g_ab[(long)p * 2 * HID_ + i];
        float b = g_ab[(long)p * 2 * HID_ + HID_ + i];
        g_gact[idx] = a / (1.f + expf(-a)) * b;
    }
}

__global__ void final_kernel(const int* __restrict__ inv, float* __restrict__ out)
{
    long idx = (long)blockIdx.x * blockDim.x + threadIdx.x;
    if (idx < (long)T_ * C_) {
        int t = (int)(idx >> 10), c = (int)(idx & (C_ - 1));
        int p = inv[t];
        out[idx] = g_x[idx] + g_xp[(long)p * C_ + c] - g_xp0[(long)p * C_ + c];
    }
}

#define GETSYM(p, var) cudaGetSymbolAddress((void**)&(p), var)

extern "C" void kernel_launch(void* const* d_in, const int* in_sizes, int n_in,
                              void* d_out, int out_size)
{
    const float* feats   = (const float*)d_in[0];
    const float* mod     = (const float*)d_in[1];
    const float* context = (const float*)d_in[2];
    const float* Wq  = (const float*)d_in[3];
    const float* bq  = (const float*)d_in[4];
    const float* Wkv = (const float*)d_in[5];
    const float* bkv = (const float*)d_in[6];
    const float* Wo  = (const float*)d_in[7];
    const float* bo  = (const float*)d_in[8];
    const float* qg  = (const float*)d_in[9];
    const float* kg  = (const float*)d_in[10];
    const float* Wcq = (const float*)d_in[11];
    const float* bcq = (const float*)d_in[12];
    const float* Wckv= (const float*)d_in[13];
    const float* bckv= (const float*)d_in[14];
    const float* Wco = (const float*)d_in[15];
    const float* bco = (const float*)d_in[16];
    const float* W12 = (const float*)d_in[17];
    const float* b12 = (const float*)d_in[18];
    const float* W3  = (const float*)d_in[19];
    const float* b3  = (const float*)d_in[20];
    const float* Wm  = (const float*)d_in[21];
    const float* bm  = (const float*)d_in[22];
    const int* coords  = (const int*)d_in[23];
    const int* inverse = (const int*)d_in[24];
    const int* pcoords = (const int*)d_in[25];
    float* out = (float*)d_out;

    float *p_m, *p_h, *p_q, *p_o, *p_x, *p_S, *p_hp, *p_kv, *p_xp0, *p_xp,
          *p_hp2, *p_cq, *p_ckv, *p_S2, *p_co, *p_ab, *p_gact;
    int* p_cnt;
    GETSYM(p_m, g_m);   GETSYM(p_h, g_h);   GETSYM(p_q, g_q);   GETSYM(p_o, g_o);
    GETSYM(p_x, g_x);   GETSYM(p_S, g_S);   GETSYM(p_hp, g_hp); GETSYM(p_kv, g_kv);
    GETSYM(p_xp0, g_xp0); GETSYM(p_xp, g_xp); GETSYM(p_hp2, g_hp2);
    GETSYM(p_cq, g_cq); GETSYM(p_ckv, g_ckv); GETSYM(p_S2, g_S2); GETSYM(p_co, g_co);
    GETSYM(p_ab, g_ab); GETSYM(p_gact, g_gact); GETSYM(p_cnt, g_cnt);

    modproj_kernel<<<(NM_ + 255) / 256, 256>>>(mod, Wm, bm);

    cudaMemsetAsync(p_cnt, 0, P_ * sizeof(int));
    build_members_kernel<<<T_ / 256, 256>>>(inverse);
    sort_members_kernel<<<2, 256>>>();

    ln_mod_kernel<<<T_, 256>>>(feats, p_h, p_m + C_, p_m);

    gemm_kernel<false, 0><<<dim3(C_ / 128, T_ / 128, 1), 256>>>(
        T_, C_, C_, p_h, C_, 0, Wq, C_, 1, 0, p_q, C_, 0, bq, nullptr, 0, nullptr);

    seg_mean_kernel<<<P_, 256>>>(p_h, p_hp, nullptr);
    gemm_kernel<false, 0><<<dim3(2 * C_ / 128, P_ / 128, 1), 256>>>(
        P_, 2 * C_, C_, p_hp, C_, 0, Wkv, 2 * C_, 1, 0, p_kv, 2 * C_, 0, bkv,
        nullptr, 0, nullptr);

    rope_norm_kernel<<<(T_ * H_ * 32) / 256, 256>>>(p_q, C_, T_, coords, 1, qg);
    rope_norm_kernel<<<(P_ * H_ * 32) / 256, 256>>>(p_kv, 2 * C_, P_, pcoords, 4, kg);

    gemm_kernel<true, 0><<<dim3(P_ / 128, T_ / 128, H_), 256>>>(
        T_, P_, D_, p_q, C_, 64, p_kv, 1, 2 * C_, 64,
        p_S, P_, (long)T_ * P_, nullptr, nullptr, 0, nullptr);
    softmax_kernel<16><<<(H_ * T_) / 8, 256>>>(p_S, (long)H_ * T_, 0.125f);

    gemm_kernel<false, 0><<<dim3(1, T_ / 128, H_), 256>>>(
        T_, D_, P_, p_S, P_, (long)T_ * P_, p_kv + C_, 2 * C_, 1, 64,
        p_o, C_, 64, nullptr, nullptr, 0, nullptr);

    gemm_kernel<false, 1><<<dim3(C_ / 128, T_ / 128, 1), 256>>>(
        T_, C_, C_, p_o, C_, 0, Wo, C_, 1, 0, p_x, C_, 0, bo, feats, C_, p_m + 2 * C_);

    seg_mean_kernel<<<P_, 256>>>(p_x, p_xp0, p_xp);
    ln_mod_kernel<<<P_, 256>>>(p_xp, p_hp2, p_m + 4 * C_, p_m + 3 * C_);
    gemm_kernel<false, 0><<<dim3(C_ / 128, P_ / 128, 1), 256>>>(
        P_, C_, C_, p_hp2, C_, 0, Wcq, C_, 1, 0, p_cq, C_, 0, bcq, nullptr, 0, nullptr);
    gemm_kernel<false, 0><<<dim3(2 * C_ / 128, L_ / 128, 1), 256>>>(
        L_, 2 * C_, C_, context, C_, 0, Wckv, 2 * C_, 1, 0, p_ckv, 2 * C_, 0, bckv,
        nullptr, 0, nullptr);

    gemm_kernel<true, 0><<<dim3(L_ / 128, P_ / 128, H_), 256>>>(
        P_, L_, D_, p_cq, C_, 64, p_ckv, 1, 2 * C_, 64,
        p_S2, L_, (long)P_ * L_, nullptr, nullptr, 0, nullptr);
    softmax_kernel<32><<<(H_ * P_) / 8, 256>>>(p_S2, (long)H_ * P_, 0.125f);
    gemm_kernel<false, 0><<<dim3(1, P_ / 128, H_), 256>>>(
        P_, D_, L_, p_S2, L_, (long)P_ * L_, p_ckv + C_, 2 * C_, 1, 64,
        p_co, C_, 64, nullptr, nullptr, 0, nullptr);

    gemm_kernel<false, 1><<<dim3(C_ / 128, P_ / 128, 1), 256>>>(
        P_, C_, C_, p_co, C_, 0, Wco, C_, 1, 0, p_xp, C_, 0, bco, p_xp, C_,
        p_m + 5 * C_);

    ln_mod_kernel<<<P_, 256>>>(p_xp, p_hp2, p_m + 7 * C_, p_m + 6 * C_);
    gemm_kernel<false, 0><<<dim3(2 * HID_ / 128, P_ / 128, 1), 256>>>(
        P_, 2 * HID_, C_, p_hp2, C_, 0, W12, 2 * HID_, 1, 0, p_ab, 2 * HID_, 0, b12,
        nullptr, 0, nullptr);
    silugate_kernel<<<(P_ * HID_) / 256, 256>>>();
    gemm_kernel<false, 1><<<dim3(C_ / 128, P_ / 128, 1), 256>>>(
        P_, C_, HID_, p_gact, HID_, 0, W3, C_, 1, 0, p_xp, C_, 0, b3, p_xp, C_,
        p_m + 8 * C_);

    final_kernel<<<((long)T_ * C_) / 256, 256>>>(inverse, out);
}

// round 2
// speedup vs baseline: 2.5815x; 2.5815x over previous
#include <cuda_runtime.h>
#include <cuda_bf16.h>
#include <math.h>
#include <stdint.h>

#define T_   16384
#define C_   1024
#define H_   16
#define D_   64
#define P_   512
#define L_   1024
#define HID_ 4096
#define NM_  9216

__device__ float g_m[NM_];
__device__ float g_h[(size_t)T_ * C_];
__device__ float g_q[(size_t)T_ * C_];
__device__ float g_o[(size_t)T_ * C_];
__device__ float g_x[(size_t)T_ * C_];
__device__ float g_S[(size_t)H_ * T_ * P_];
__device__ float g_hp[(size_t)P_ * C_];
__device__ float g_kv[(size_t)P_ * 2 * C_];
__device__ float g_xp0[(size_t)P_ * C_];
__device__ float g_xp[(size_t)P_ * C_];
__device__ float g_hp2[(size_t)P_ * C_];
__device__ float g_cq[(size_t)P_ * C_];
__device__ float g_ckv[(size_t)L_ * 2 * C_];
__device__ float g_S2[(size_t)H_ * P_ * L_];
__device__ float g_co[(size_t)P_ * C_];
__device__ float g_ab[(size_t)P_ * 2 * HID_];
__device__ float g_gact[(size_t)P_ * HID_];
__device__ int   g_cnt[P_];
__device__ int   g_members[P_ * 64];

__device__ __forceinline__ uint32_t f2tf(float f) {
    uint32_t u;
    asm("cvt.rna.tf32.f32 %0, %1;" : "=r"(u) : "f"(f));
    return u;
}

__device__ __forceinline__ void mma_tf32(float* c, const uint32_t* a, const uint32_t* b) {
    asm volatile(
        "mma.sync.aligned.m16n8k8.row.col.f32.tf32.tf32.f32 "
        "{%0,%1,%2,%3}, {%4,%5,%6,%7}, {%8,%9}, {%0,%1,%2,%3};\n"
        : "+f"(c[0]), "+f"(c[1]), "+f"(c[2]), "+f"(c[3])
        : "r"(a[0]), "r"(a[1]), "r"(a[2]), "r"(a[3]), "r"(b[0]), "r"(b[1]));
}

// Tensor-core GEMM: C[m][n] = sum_k A[m][k]*B[k][n] (+bias) ; EPI=1: resid + v*gate
// A row-major (lda). B strided: B[k][n] = Bb[k*bKs + n*bNs].
// BT=true  : k contiguous in B (bKs==1) -> vectorize along k
// BT=false : n contiguous in B (bNs==1) -> vectorize along n
// Requires: M % 128 == 0, K % 32 == 0, lda%4==0, (BT? bNs%4==0 : bKs%4==0).
template<bool BT, int EPI>
__global__ __launch_bounds__(256)
void gemm_tc(int M, int N, int K,
             const float* __restrict__ A, int lda, long aB,
             const float* __restrict__ B, int bKs, int bNs, long bB,
             float* __restrict__ Cp, int ldc, long cB,
             const float* __restrict__ bias,
             const float* __restrict__ resid, int ldr,
             const float* __restrict__ gate)
{
    const int BM = 128, BN = 128, BK = 32;
    __shared__ uint32_t As[BK][BM + 8];
    __shared__ uint32_t Bs[BK][BN + 8];

    int bz = blockIdx.z;
    const float* Ab = A + (long)bz * aB;
    const float* Bb = B + (long)bz * bB;
    float*       Cb = Cp + (long)bz * cB;
    int row0 = blockIdx.y * BM;
    int col0 = blockIdx.x * BN;
    int tid  = threadIdx.x;
    int lane = tid & 31;
    int wid  = tid >> 5;
    int lr = lane >> 2, lc = lane & 3;
    int warpM = (wid & 1) * 64;
    int warpN = (wid >> 1) * 32;

    float acc[4][4][4];
#pragma unroll
    for (int i = 0; i < 4; i++)
#pragma unroll
        for (int j = 0; j < 4; j++)
#pragma unroll
            for (int r = 0; r < 4; r++) acc[i][j][r] = 0.f;

    // load indices
    int aq = tid & 7, am = tid >> 3;        // A: k-quad, m (32 rows/pass)
    int nq = tid & 31, bk = tid >> 5;       // B NN: n-quad, k (8 rows/pass)

    for (int k0 = 0; k0 < K; k0 += BK) {
        // ---- A tile: [BM x BK] -> As[k][m], float4 along k ----
#pragma unroll
        for (int i = 0; i < 4; i++) {
            int m = am + 32 * i;
            const float4 v = *reinterpret_cast<const float4*>(
                Ab + (long)(row0 + m) * lda + k0 + aq * 4);
            As[aq * 4 + 0][m] = f2tf(v.x);
            As[aq * 4 + 1][m] = f2tf(v.y);
            As[aq * 4 + 2][m] = f2tf(v.z);
            As[aq * 4 + 3][m] = f2tf(v.w);
        }
        // ---- B tile ----
        if (BT) {
            // k contiguous: float4 along k, per n
#pragma unroll
            for (int i = 0; i < 4; i++) {
                int n = am + 32 * i;
                int gn = col0 + n;
                const float4 v = *reinterpret_cast<const float4*>(
                    Bb + (long)gn * bNs + k0 + aq * 4);
                Bs[aq * 4 + 0][n] = f2tf(v.x);
                Bs[aq * 4 + 1][n] = f2tf(v.y);
                Bs[aq * 4 + 2][n] = f2tf(v.z);
                Bs[aq * 4 + 3][n] = f2tf(v.w);
            }
        } else {
            // n contiguous: float4 along n, per k
#pragma unroll
            for (int i = 0; i < 4; i++) {
                int kk = bk + 8 * i;
                int gn = col0 + nq * 4;
                float4 v;
                if (gn < N) {
                    v = *reinterpret_cast<const float4*>(
                        Bb + (long)(k0 + kk) * bKs + gn);
                } else {
                    v = make_float4(0.f, 0.f, 0.f, 0.f);
                }
                Bs[kk][nq * 4 + 0] = f2tf(v.x);
                Bs[kk][nq * 4 + 1] = f2tf(v.y);
                Bs[kk][nq * 4 + 2] = f2tf(v.z);
                Bs[kk][nq * 4 + 3] = f2tf(v.w);
            }
        }
        __syncthreads();

#pragma unroll
        for (int kk = 0; kk < 4; kk++) {
            uint32_t a[4][4], b[4][2];
#pragma unroll
            for (int mi = 0; mi < 4; mi++) {
                int m = warpM + mi * 16 + lr;
                a[mi][0] = As[kk * 8 + lc][m];
                a[mi][1] = As[kk * 8 + lc][m + 8];
                a[mi][2] = As[kk * 8 + lc + 4][m];
                a[mi][3] = As[kk * 8 + lc + 4][m + 8];
            }
#pragma unroll
            for (int ni = 0; ni < 4; ni++) {
                int n = warpN + ni * 8 + lr;
                b[ni][0] = Bs[kk * 8 + lc][n];
                b[ni][1] = Bs[kk * 8 + lc + 4][n];
            }
#pragma unroll
            for (int mi = 0; mi < 4; mi++)
#pragma unroll
                for (int ni = 0; ni < 4; ni++)
                    mma_tf32(acc[mi][ni], a[mi], b[ni]);
        }
        __syncthreads();
    }

    // epilogue: c0 (r,c0), c1 (r,c0+1), c2 (r+8,c0), c3 (r+8,c0+1)
#pragma unroll
    for (int mi = 0; mi < 4; mi++) {
#pragma unroll
        for (int ni = 0; ni < 4; ni++) {
            int gm0 = row0 + warpM + mi * 16 + lr;
            int gn  = col0 + warpN + ni * 8 + lc * 2;
            if (gn >= N) continue;
#pragma unroll
            for (int half = 0; half < 2; half++) {
                int gm = gm0 + half * 8;
                float v0 = acc[mi][ni][half * 2 + 0];
                float v1 = acc[mi][ni][half * 2 + 1];
                if (bias) { v0 += bias[gn]; v1 += bias[gn + 1]; }
                if (EPI == 1) {
                    const float2 rr = *reinterpret_cast<const float2*>(
                        resid + (long)gm * ldr + gn);
                    v0 = rr.x + v0 * gate[gn];
                    v1 = rr.y + v1 * gate[gn + 1];
                }
                *reinterpret_cast<float2*>(Cb + (long)gm * ldc + gn) =
                    make_float2(v0, v1);
            }
        }
    }
}

__global__ void modproj_kernel(const float* __restrict__ mod,
                               const float* __restrict__ Wm,
                               const float* __restrict__ bm)
{
    __shared__ float sm[C_];
    for (int i = threadIdx.x; i < C_; i += blockDim.x) {
        float v = mod[i];
        sm[i] = v / (1.f + expf(-v));
    }
    __syncthreads();
    int j = blockIdx.x * blockDim.x + threadIdx.x;
    if (j < NM_) {
        float acc = bm[j];
        for (int i = 0; i < C_; i++) acc += sm[i] * Wm[(long)i * NM_ + j];
        g_m[j] = acc;
    }
}

__global__ void ln_mod_kernel(const float* __restrict__ in, float* __restrict__ out,
                              const float* __restrict__ sc, const float* __restrict__ sh)
{
    __shared__ float rs[256], rs2[256];
    int r = blockIdx.x, tid = threadIdx.x;
    const float* x = in + (long)r * C_;
    float v[4], s = 0.f, s2 = 0.f;
#pragma unroll
    for (int i = 0; i < 4; i++) { v[i] = x[tid + i * 256]; s += v[i]; s2 += v[i] * v[i]; }
    rs[tid] = s; rs2[tid] = s2; __syncthreads();
    for (int o = 128; o; o >>= 1) {
        if (tid < o) { rs[tid] += rs[tid + o]; rs2[tid] += rs2[tid + o]; }
        __syncthreads();
    }
    float mu = rs[0] * (1.f / C_);
    float var = rs2[0] * (1.f / C_) - mu * mu;
    float rstd = rsqrtf(fmaxf(var, 0.f) + 1e-6f);
#pragma unroll
    for (int i = 0; i < 4; i++) {
        int c = tid + i * 256;
        out[(long)r * C_ + c] = (v[i] - mu) * rstd * (1.f + sc[c]) + sh[c];
    }
}

__global__ void build_members_kernel(const int* __restrict__ inv)
{
    int t = blockIdx.x * blockDim.x + threadIdx.x;
    if (t < T_) {
        int p = inv[t];
        int s = atomicAdd(&g_cnt[p], 1);
        if (s < 64) g_members[p * 64 + s] = t;
    }
}

__global__ void sort_members_kernel()
{
    int p = blockIdx.x * blockDim.x + threadIdx.x;
    if (p < P_) {
        int n = min(g_cnt[p], 64);
        int* a = &g_members[p * 64];
        for (int i = 1; i < n; i++) {
            int key = a[i], j = i - 1;
            while (j >= 0 && a[j] > key) { a[j + 1] = a[j]; --j; }
            a[j + 1] = key;
        }
    }
}

__global__ void seg_mean_kernel(const float* __restrict__ in, float* __restrict__ out,
                                float* __restrict__ out2)
{
    int p = blockIdx.x, tid = threadIdx.x;
    int n = min(g_cnt[p], 64);
    float acc[4] = {0.f, 0.f, 0.f, 0.f};
    for (int j = 0; j < n; j++) {
        long base = (long)g_members[p * 64 + j] * C_;
#pragma unroll
        for (int i = 0; i < 4; i++) acc[i] += in[base + tid + i * 256];
    }
    float invn = n ? 1.f / n : 0.f;
#pragma unroll
    for (int i = 0; i < 4; i++) {
        float val = acc[i] * invn;
        out[(long)p * C_ + tid + i * 256] = val;
        if (out2) out2[(long)p * C_ + tid + i * 256] = val;
    }
}

__global__ void rope_norm_kernel(float* __restrict__ x, int rowStride, int rows,
                                 const int* __restrict__ coords, int cmult,
                                 const float* __restrict__ gamma)
{
    long gw = ((long)blockIdx.x * blockDim.x + threadIdx.x) >> 5;
    if (gw >= (long)rows * H_) return;
    int lane = threadIdx.x & 31;
    int t = (int)(gw / H_), h = (int)(gw % H_);
    float* base = x + (long)t * rowStride + h * D_;
    float x0 = base[2 * lane], x1 = base[2 * lane + 1];
    float c = 1.f, s = 0.f;
    if (lane < 30) {
        int a = lane / 10, f = lane % 10;
        float freq = powf(10000.f, -(float)f * 0.1f);
        float ang = (float)(coords[t * 3 + a] * cmult) * freq;
        c = cosf(ang); s = sinf(ang);
    }
    float re = x0 * c - x1 * s;
    float im = x0 * s + x1 * c;
    float ss = re * re + im * im;
#pragma unroll
    for (int o = 16; o; o >>= 1) ss += __shfl_xor_sync(0xffffffffu, ss, o);
    float nrm = sqrtf(ss);
    float scl = 8.f / fmaxf(nrm, 1e-12f);
    base[2 * lane]     = re * scl * gamma[h * D_ + 2 * lane];
    base[2 * lane + 1] = im * scl * gamma[h * D_ + 2 * lane + 1];
}

template<int PER>
__global__ void softmax_kernel(float* __restrict__ S, long rows, float scale)
{
    long gw = ((long)blockIdx.x * blockDim.x + threadIdx.x) >> 5;
    if (gw >= rows) return;
    int lane = threadIdx.x & 31;
    float* row = S + gw * (PER * 32);
    float v[PER], mx = -1e30f;
#pragma unroll
    for (int i = 0; i < PER; i++) { v[i] = row[lane + i * 32] * scale; mx = fmaxf(mx, v[i]); }
#pragma unroll
    for (int o = 16; o; o >>= 1) mx = fmaxf(mx, __shfl_xor_sync(0xffffffffu, mx, o));
    float s = 0.f;
#pragma unroll
    for (int i = 0; i < PER; i++) { v[i] = expf(v[i] - mx); s += v[i]; }
#pragma unroll
    for (int o = 16; o; o >>= 1) s += __shfl_xor_sync(0xffffffffu, s, o);
    float inv = 1.f / s;
#pragma unroll
    for (int i = 0; i < PER; i++) row[lane + i * 32] = v[i] * inv;
}

__global__ void silugate_kernel()
{
    long idx = (long)blockIdx.x * blockDim.x + threadIdx.x;
    if (idx < (long)P_ * HID_) {
        int p = (int)(idx >> 12), i = (int)(idx & (HID_ - 1));
        float a = g_ab[(long)p * 2 * HID_ + i];
        float b = g_ab[(long)p * 2 * HID_ + HID_ + i];
        g_gact[idx] = a / (1.f + expf(-a)) * b;
    }
}

__global__ void final_kernel(const int* __restrict__ inv, float* __restrict__ out)
{
    long idx = (long)blockIdx.x * blockDim.x + threadIdx.x;
    if (idx < (long)T_ * C_) {
        int t = (int)(idx >> 10), c = (int)(idx & (C_ - 1));
        int p = inv[t];
        out[idx] = g_x[idx] + g_xp[(long)p * C_ + c] - g_xp0[(long)p * C_ + c];
    }
}

#define GETSYM(p, var) cudaGetSymbolAddress((void**)&(p), var)

extern "C" void kernel_launch(void* const* d_in, const int* in_sizes, int n_in,
                              void* d_out, int out_size)
{
    const float* feats   = (const float*)d_in[0];
    const float* mod     = (const float*)d_in[1];
    const float* context = (const float*)d_in[2];
    const float* Wq  = (const float*)d_in[3];
    const float* bq  = (const float*)d_in[4];
    const float* Wkv = (const float*)d_in[5];
    const float* bkv = (const float*)d_in[6];
    const float* Wo  = (const float*)d_in[7];
    const float* bo  = (const float*)d_in[8];
    const float* qg  = (const float*)d_in[9];
    const float* kg  = (const float*)d_in[10];
    const float* Wcq = (const float*)d_in[11];
    const float* bcq = (const float*)d_in[12];
    const float* Wckv= (const float*)d_in[13];
    const float* bckv= (const float*)d_in[14];
    const float* Wco = (const float*)d_in[15];
    const float* bco = (const float*)d_in[16];
    const float* W12 = (const float*)d_in[17];
    const float* b12 = (const float*)d_in[18];
    const float* W3  = (const float*)d_in[19];
    const float* b3  = (const float*)d_in[20];
    const float* Wm  = (const float*)d_in[21];
    const float* bm  = (const float*)d_in[22];
    const int* coords  = (const int*)d_in[23];
    const int* inverse = (const int*)d_in[24];
    const int* pcoords = (const int*)d_in[25];
    float* out = (float*)d_out;

    float *p_m, *p_h, *p_q, *p_o, *p_x, *p_S, *p_hp, *p_kv, *p_xp0, *p_xp,
          *p_hp2, *p_cq, *p_ckv, *p_S2, *p_co, *p_ab, *p_gact;
    int* p_cnt;
    GETSYM(p_m, g_m);   GETSYM(p_h, g_h);   GETSYM(p_q, g_q);   GETSYM(p_o, g_o);
    GETSYM(p_x, g_x);   GETSYM(p_S, g_S);   GETSYM(p_hp, g_hp); GETSYM(p_kv, g_kv);
    GETSYM(p_xp0, g_xp0); GETSYM(p_xp, g_xp); GETSYM(p_hp2, g_hp2);
    GETSYM(p_cq, g_cq); GETSYM(p_ckv, g_ckv); GETSYM(p_S2, g_S2); GETSYM(p_co, g_co);
    GETSYM(p_ab, g_ab); GETSYM(p_gact, g_gact); GETSYM(p_cnt, g_cnt);

    modproj_kernel<<<(NM_ + 255) / 256, 256>>>(mod, Wm, bm);

    cudaMemsetAsync(p_cnt, 0, P_ * sizeof(int));
    build_members_kernel<<<T_ / 256, 256>>>(inverse);
    sort_members_kernel<<<2, 256>>>();

    ln_mod_kernel<<<T_, 256>>>(feats, p_h, p_m + C_, p_m);

    // q = h @ Wq + bq
    gemm_tc<false, 0><<<dim3(C_ / 128, T_ / 128, 1), 256>>>(
        T_, C_, C_, p_h, C_, 0, Wq, C_, 1, 0, p_q, C_, 0, bq, nullptr, 0, nullptr);

    seg_mean_kernel<<<P_, 256>>>(p_h, p_hp, nullptr);
    gemm_tc<false, 0><<<dim3(2 * C_ / 128, P_ / 128, 1), 256>>>(
        P_, 2 * C_, C_, p_hp, C_, 0, Wkv, 2 * C_, 1, 0, p_kv, 2 * C_, 0, bkv,
        nullptr, 0, nullptr);

    rope_norm_kernel<<<(T_ * H_ * 32) / 256, 256>>>(p_q, C_, T_, coords, 1, qg);
    rope_norm_kernel<<<(P_ * H_ * 32) / 256, 256>>>(p_kv, 2 * C_, P_, pcoords, 4, kg);

    // S[h] = Q_h @ K_h^T
    gemm_tc<true, 0><<<dim3(P_ / 128, T_ / 128, H_), 256>>>(
        T_, P_, D_, p_q, C_, 64, p_kv, 1, 2 * C_, 64,
        p_S, P_, (long)T_ * P_, nullptr, nullptr, 0, nullptr);
    softmax_kernel<16><<<(H_ * T_) / 8, 256>>>(p_S, (long)H_ * T_, 0.125f);

    // O[h] = S_h @ V_h
    gemm_tc<false, 0><<<dim3(1, T_ / 128, H_), 256>>>(
        T_, D_, P_, p_S, P_, (long)T_ * P_, p_kv + C_, 2 * C_, 1, 64,
        p_o, C_, 64, nullptr, nullptr, 0, nullptr);

    // x = feats + (o @ Wo + bo) * g_msa
    gemm_tc<false, 1><<<dim3(C_ / 128, T_ / 128, 1), 256>>>(
        T_, C_, C_, p_o, C_, 0, Wo, C_, 1, 0, p_x, C_, 0, bo, feats, C_, p_m + 2 * C_);

    seg_mean_kernel<<<P_, 256>>>(p_x, p_xp0, p_xp);
    ln_mod_kernel<<<P_, 256>>>(p_xp, p_hp2, p_m + 4 * C_, p_m + 3 * C_);
    gemm_tc<false, 0><<<dim3(C_ / 128, P_ / 128, 1), 256>>>(
        P_, C_, C_, p_hp2, C_, 0, Wcq, C_, 1, 0, p_cq, C_, 0, bcq, nullptr, 0, nullptr);
    gemm_tc<false, 0><<<dim3(2 * C_ / 128, L_ / 128, 1), 256>>>(
        L_, 2 * C_, C_, context, C_, 0, Wckv, 2 * C_, 1, 0, p_ckv, 2 * C_, 0, bckv,
        nullptr, 0, nullptr);

    gemm_tc<true, 0><<<dim3(L_ / 128, P_ / 128, H_), 256>>>(
        P_, L_, D_, p_cq, C_, 64, p_ckv, 1, 2 * C_, 64,
        p_S2, L_, (long)P_ * L_, nullptr, nullptr, 0, nullptr);
    softmax_kernel<32><<<(H_ * P_) / 8, 256>>>(p_S2, (long)H_ * P_, 0.125f);
    gemm_tc<false, 0><<<dim3(1, P_ / 128, H_), 256>>>(
        P_, D_, L_, p_S2, L_, (long)P_ * L_, p_ckv + C_, 2 * C_, 1, 64,
        p_co, C_, 64, nullptr, nullptr, 0, nullptr);

    gemm_tc<false, 1><<<dim3(C_ / 128, P_ / 128, 1), 256>>>(
        P_, C_, C_, p_co, C_, 0, Wco, C_, 1, 0, p_xp, C_, 0, bco, p_xp, C_,
        p_m + 5 * C_);

    ln_mod_kernel<<<P_, 256>>>(p_xp, p_hp2, p_m + 7 * C_, p_m + 6 * C_);
    gemm_tc<false, 0><<<dim3(2 * HID_ / 128, P_ / 128, 1), 256>>>(
        P_, 2 * HID_, C_, p_hp2, C_, 0, W12, 2 * HID_, 1, 0, p_ab, 2 * HID_, 0, b12,
        nullptr, 0, nullptr);
    silugate_kernel<<<(P_ * HID_) / 256, 256>>>();
    gemm_tc<false, 1><<<dim3(C_ / 128, P_ / 128, 1), 256>>>(
        P_, C_, HID_, p_gact, HID_, 0, W3, C_, 1, 0, p_xp, C_, 0, b3, p_xp, C_,
        p_m + 8 * C_);

    final_kernel<<<((long)T_ * C_) / 256, 256>>>(inverse, out);
}

// round 3
// speedup vs baseline: 3.5136x; 1.3611x over previous
#include <cuda_runtime.h>
#include <cuda_bf16.h>
#include <math.h>
#include <stdint.h>

#define T_   16384
#define C_   1024
#define H_   16
#define D_   64
#define P_   512
#define L_   1024
#define HID_ 4096
#define NM_  9216

__device__ float g_m[NM_];
__device__ float g_h[(size_t)T_ * C_];
__device__ float g_q[(size_t)T_ * C_];
__device__ float g_o[(size_t)T_ * C_];
__device__ float g_x[(size_t)T_ * C_];
__device__ float g_S[(size_t)H_ * T_ * P_];
__device__ float g_hp[(size_t)P_ * C_];
__device__ float g_kv[(size_t)P_ * 2 * C_];
__device__ float g_xp0[(size_t)P_ * C_];
__device__ float g_xp[(size_t)P_ * C_];
__device__ float g_hp2[(size_t)P_ * C_];
__device__ float g_cq[(size_t)P_ * C_];
__device__ float g_ckv[(size_t)L_ * 2 * C_];
__device__ float g_S2[(size_t)H_ * P_ * L_];
__device__ float g_co[(size_t)P_ * C_];
__device__ float g_ab[(size_t)P_ * 2 * HID_];
__device__ float g_gact[(size_t)P_ * HID_];
__device__ int   g_cnt[P_];
__device__ int   g_members[P_ * 64];

__device__ __forceinline__ void cp16(uint32_t s, const float* g) {
    asm volatile("cp.async.ca.shared.global [%0], [%1], 16;\n" :: "r"(s), "l"(g));
}
__device__ __forceinline__ void cp_commit() {
    asm volatile("cp.async.commit_group;\n");
}
template<int N>
__device__ __forceinline__ void cp_wait() {
    asm volatile("cp.async.wait_group %0;\n" :: "n"(N));
}

__device__ __forceinline__ void mma_tf32(float* c, const uint32_t* a, const uint32_t* b) {
    asm volatile(
        "mma.sync.aligned.m16n8k8.row.col.f32.tf32.tf32.f32 "
        "{%0,%1,%2,%3}, {%4,%5,%6,%7}, {%8,%9}, {%0,%1,%2,%3};\n"
        : "+f"(c[0]), "+f"(c[1]), "+f"(c[2]), "+f"(c[3])
        : "r"(a[0]), "r"(a[1]), "r"(a[2]), "r"(a[3]), "r"(b[0]), "r"(b[1]));
}

// Pipelined tensor-core GEMM.
// C[m][n] = sum_k A[m][k]*B[k][n] (+bias) ; EPI=1: out = resid + v*gate
// A row-major (lda). B strided: B[k][n] = Bb[k*bKs + n*bNs].
// BT=true : bKs==1 (k contiguous). BT=false : bNs==1 (n contiguous).
// Requirements: M%128==0, N%BN==0, K%32==0, all base ptrs/strides 16B-aligned.
template<bool BT, int EPI, int BN>
__global__ __launch_bounds__(256)
void gemm_tc(int M, int N, int K,
             const float* __restrict__ A, int lda, long aB,
             const float* __restrict__ B, int bKs, int bNs, long bB,
             float* __restrict__ Cp, int ldc, long cB,
             const float* __restrict__ bias,
             const float* __restrict__ resid, int ldr,
             const float* __restrict__ gate)
{
    constexpr int BM = 128, BK = 32, STAGES = 3;
    constexpr int LDA = BK + 4;                         // 36 floats per m-row
    constexpr int SB  = BT ? (BN * LDA) : (BK * (BN + 8));
    constexpr int SA  = BM * LDA;
    extern __shared__ float sm_[];
    float* As = sm_;                                    // [STAGES][BM][LDA]
    float* Bs = sm_ + STAGES * SA;                      // [STAGES][...]

    const int bz = blockIdx.z;
    const float* Ab = A + (long)bz * aB;
    const float* Bb = B + (long)bz * bB;
    float*       Cb = Cp + (long)bz * cB;
    const int row0 = blockIdx.y * BM;
    const int col0 = blockIdx.x * BN;
    const int tid  = threadIdx.x;
    const int lane = tid & 31;
    const int wid  = tid >> 5;
    const int lr = lane >> 2, lc = lane & 3;

    constexpr int MI = (BN == 128) ? 4 : 2;             // warp tile M /16
    constexpr int NI = 4;                               // warp tile N /8
    int warpM, warpN;
    if (BN == 128) { warpM = (wid & 1) * 64; warpN = (wid >> 1) * 32; }
    else           { warpM = (wid & 3) * 32; warpN = (wid >> 2) * 32; }

    float acc[MI][NI][4];
#pragma unroll
    for (int i = 0; i < MI; i++)
#pragma unroll
        for (int j = 0; j < NI; j++)
#pragma unroll
            for (int r = 0; r < 4; r++) acc[i][j][r] = 0.f;

    // ---- async load helpers ----
    const int aq = tid & 7;            // k-quad
    const int am = tid >> 3;           // 0..31 (m rows, 4 passes)
    const uint32_t smemA0 = (uint32_t)__cvta_generic_to_shared(As);
    const uint32_t smemB0 = (uint32_t)__cvta_generic_to_shared(Bs);

    auto loadA = [&](int stage, int k0) {
        uint32_t base = smemA0 + (uint32_t)(stage * SA) * 4u;
#pragma unroll
        for (int i = 0; i < 4; i++) {
            int m = am + 32 * i;
            cp16(base + (uint32_t)(m * LDA + aq * 4) * 4u,
                 Ab + (long)(row0 + m) * lda + k0 + aq * 4);
        }
    };
    auto loadB = [&](int stage, int k0) {
        uint32_t base = smemB0 + (uint32_t)(stage * SB) * 4u;
        if (BT) {
#pragma unroll
            for (int i = 0; i < BN / 32; i++) {
                int n = am + 32 * i;
                cp16(base + (uint32_t)(n * LDA + aq * 4) * 4u,
                     Bb + (long)(col0 + n) * bNs + k0 + aq * 4);
            }
        } else if (BN == 128) {
            int nq = tid & 31, bk = tid >> 5;
#pragma unroll
            for (int i = 0; i < 4; i++) {
                int kk = bk + 8 * i;
                cp16(base + (uint32_t)(kk * (BN + 8) + nq * 4) * 4u,
                     Bb + (long)(k0 + kk) * bKs + col0 + nq * 4);
            }
        } else {
            int nq = tid & 15, bk = tid >> 4;
#pragma unroll
            for (int i = 0; i < 2; i++) {
                int kk = bk + 16 * i;
                cp16(base + (uint32_t)(kk * (BN + 8) + nq * 4) * 4u,
                     Bb + (long)(k0 + kk) * bKs + col0 + nq * 4);
            }
        }
    };

    const int nkt = K / BK;
    // prologue
#pragma unroll
    for (int s = 0; s < STAGES - 1; s++) {
        if (s < nkt) { loadA(s, s * BK); loadB(s, s * BK); }
        cp_commit();
    }

    for (int kt = 0; kt < nkt; kt++) {
        cp_wait<STAGES - 2>();
        __syncthreads();
        int kn = kt + STAGES - 1;
        if (kn < nkt) { loadA(kn % STAGES, kn * BK); loadB(kn % STAGES, kn * BK); }
        cp_commit();

        const float* Asb = As + (kt % STAGES) * SA;
        const float* Bsb = Bs + (kt % STAGES) * SB;
#pragma unroll
        for (int kk = 0; kk < 4; kk++) {
            uint32_t a[MI][4], b[NI][2];
#pragma unroll
            for (int mi = 0; mi < MI; mi++) {
                int m = warpM + mi * 16 + lr;
                a[mi][0] = __float_as_uint(Asb[m * LDA + kk * 8 + lc]);
                a[mi][1] = __float_as_uint(Asb[(m + 8) * LDA + kk * 8 + lc]);
                a[mi][2] = __float_as_uint(Asb[m * LDA + kk * 8 + lc + 4]);
                a[mi][3] = __float_as_uint(Asb[(m + 8) * LDA + kk * 8 + lc + 4]);
            }
#pragma unroll
            for (int ni = 0; ni < NI; ni++) {
                int n = warpN + ni * 8 + lr;
                if (BT) {
                    b[ni][0] = __float_as_uint(Bsb[n * LDA + kk * 8 + lc]);
                    b[ni][1] = __float_as_uint(Bsb[n * LDA + kk * 8 + lc + 4]);
                } else {
                    b[ni][0] = __float_as_uint(Bsb[(kk * 8 + lc) * (BN + 8) + n]);
                    b[ni][1] = __float_as_uint(Bsb[(kk * 8 + lc + 4) * (BN + 8) + n]);
                }
            }
#pragma unroll
            for (int mi = 0; mi < MI; mi++)
#pragma unroll
                for (int ni = 0; ni < NI; ni++)
                    mma_tf32(acc[mi][ni], a[mi], b[ni]);
        }
        __syncthreads();
    }

#pragma unroll
    for (int mi = 0; mi < MI; mi++) {
#pragma unroll
        for (int ni = 0; ni < NI; ni++) {
            int gm0 = row0 + warpM + mi * 16 + lr;
            int gn  = col0 + warpN + ni * 8 + lc * 2;
#pragma unroll
            for (int half = 0; half < 2; half++) {
                int gm = gm0 + half * 8;
                float v0 = acc[mi][ni][half * 2 + 0];
                float v1 = acc[mi][ni][half * 2 + 1];
                if (bias) { v0 += bias[gn]; v1 += bias[gn + 1]; }
                if (EPI == 1) {
                    const float2 rr = *reinterpret_cast<const float2*>(
                        resid + (long)gm * ldr + gn);
                    v0 = rr.x + v0 * gate[gn];
                    v1 = rr.y + v1 * gate[gn + 1];
                }
                *reinterpret_cast<float2*>(Cb + (long)gm * ldc + gn) =
                    make_float2(v0, v1);
            }
        }
    }
}

__global__ void modproj_kernel(const float* __restrict__ mod,
                               const float* __restrict__ Wm,
                               const float* __restrict__ bm)
{
    __shared__ float sm[C_];
    for (int i = threadIdx.x; i < C_; i += blockDim.x) {
        float v = mod[i];
        sm[i] = v / (1.f + expf(-v));
    }
    __syncthreads();
    int j = blockIdx.x * blockDim.x + threadIdx.x;
    if (j < NM_) {
        float acc = bm[j];
        for (int i = 0; i < C_; i++) acc += sm[i] * Wm[(long)i * NM_ + j];
        g_m[j] = acc;
    }
}

__global__ void ln_mod_kernel(const float* __restrict__ in, float* __restrict__ out,
                              const float* __restrict__ sc, const float* __restrict__ sh)
{
    __shared__ float rs[256], rs2[256];
    int r = blockIdx.x, tid = threadIdx.x;
    const float* x = in + (long)r * C_;
    float v[4], s = 0.f, s2 = 0.f;
#pragma unroll
    for (int i = 0; i < 4; i++) { v[i] = x[tid + i * 256]; s += v[i]; s2 += v[i] * v[i]; }
    rs[tid] = s; rs2[tid] = s2; __syncthreads();
    for (int o = 128; o; o >>= 1) {
        if (tid < o) { rs[tid] += rs[tid + o]; rs2[tid] += rs2[tid + o]; }
        __syncthreads();
    }
    float mu = rs[0] * (1.f / C_);
    float var = rs2[0] * (1.f / C_) - mu * mu;
    float rstd = rsqrtf(fmaxf(var, 0.f) + 1e-6f);
#pragma unroll
    for (int i = 0; i < 4; i++) {
        int c = tid + i * 256;
        out[(long)r * C_ + c] = (v[i] - mu) * rstd * (1.f + sc[c]) + sh[c];
    }
}

__global__ void build_members_kernel(const int* __restrict__ inv)
{
    int t = blockIdx.x * blockDim.x + threadIdx.x;
    if (t < T_) {
        int p = inv[t];
        int s = atomicAdd(&g_cnt[p], 1);
        if (s < 64) g_members[p * 64 + s] = t;
    }
}

__global__ void sort_members_kernel()
{
    int p = blockIdx.x * blockDim.x + threadIdx.x;
    if (p < P_) {
        int n = min(g_cnt[p], 64);
        int* a = &g_members[p * 64];
        for (int i = 1; i < n; i++) {
            int key = a[i], j = i - 1;
            while (j >= 0 && a[j] > key) { a[j + 1] = a[j]; --j; }
            a[j + 1] = key;
        }
    }
}

__global__ void seg_mean_kernel(const float* __restrict__ in, float* __restrict__ out,
                                float* __restrict__ out2)
{
    int p = blockIdx.x, tid = threadIdx.x;
    int n = min(g_cnt[p], 64);
    float acc[4] = {0.f, 0.f, 0.f, 0.f};
    for (int j = 0; j < n; j++) {
        long base = (long)g_members[p * 64 + j] * C_;
#pragma unroll
        for (int i = 0; i < 4; i++) acc[i] += in[base + tid + i * 256];
    }
    float invn = n ? 1.f / n : 0.f;
#pragma unroll
    for (int i = 0; i < 4; i++) {
        float val = acc[i] * invn;
        out[(long)p * C_ + tid + i * 256] = val;
        if (out2) out2[(long)p * C_ + tid + i * 256] = val;
    }
}

__global__ void rope_norm_kernel(float* __restrict__ x, int rowStride, int rows,
                                 const int* __restrict__ coords, int cmult,
                                 const float* __restrict__ gamma)
{
    long gw = ((long)blockIdx.x * blockDim.x + threadIdx.x) >> 5;
    if (gw >= (long)rows * H_) return;
    int lane = threadIdx.x & 31;
    int t = (int)(gw / H_), h = (int)(gw % H_);
    float* base = x + (long)t * rowStride + h * D_;
    float x0 = base[2 * lane], x1 = base[2 * lane + 1];
    float c = 1.f, s = 0.f;
    if (lane < 30) {
        int a = lane / 10, f = lane % 10;
        float freq = powf(10000.f, -(float)f * 0.1f);
        float ang = (float)(coords[t * 3 + a] * cmult) * freq;
        c = cosf(ang); s = sinf(ang);
    }
    float re = x0 * c - x1 * s;
    float im = x0 * s + x1 * c;
    float ss = re * re + im * im;
#pragma unroll
    for (int o = 16; o; o >>= 1) ss += __shfl_xor_sync(0xffffffffu, ss, o);
    float nrm = sqrtf(ss);
    float scl = 8.f / fmaxf(nrm, 1e-12f);
    base[2 * lane]     = re * scl * gamma[h * D_ + 2 * lane];
    base[2 * lane + 1] = im * scl * gamma[h * D_ + 2 * lane + 1];
}

template<int PER>
__global__ void softmax_kernel(float* __restrict__ S, long rows, float scale)
{
    long gw = ((long)blockIdx.x * blockDim.x + threadIdx.x) >> 5;
    if (gw >= rows) return;
    int lane = threadIdx.x & 31;
    float* row = S + gw * (PER * 32);
    float v[PER], mx = -1e30f;
#pragma unroll
    for (int i = 0; i < PER; i++) { v[i] = row[lane + i * 32] * scale; mx = fmaxf(mx, v[i]); }
#pragma unroll
    for (int o = 16; o; o >>= 1) mx = fmaxf(mx, __shfl_xor_sync(0xffffffffu, mx, o));
    float s = 0.f;
#pragma unroll
    for (int i = 0; i < PER; i++) { v[i] = expf(v[i] - mx); s += v[i]; }
#pragma unroll
    for (int o = 16; o; o >>= 1) s += __shfl_xor_sync(0xffffffffu, s, o);
    float inv = 1.f / s;
#pragma unroll
    for (int i = 0; i < PER; i++) row[lane + i * 32] = v[i] * inv;
}

__global__ void silugate_kernel()
{
    long idx = (long)blockIdx.x * blockDim.x + threadIdx.x;
    if (idx < (long)P_ * HID_) {
        int p = (int)(idx >> 12), i = (int)(idx & (HID_ - 1));
        float a = g_ab[(long)p * 2 * HID_ + i];
        float b = g_ab[(long)p * 2 * HID_ + HID_ + i];
        g_gact[idx] = a / (1.f + expf(-a)) * b;
    }
}

__global__ void final_kernel(const int* __restrict__ inv, float* __restrict__ out)
{
    long idx = (long)blockIdx.x * blockDim.x + threadIdx.x;
    if (idx < (long)T_ * C_) {
        int t = (int)(idx >> 10), c = (int)(idx & (C_ - 1));
        int p = inv[t];
        out[idx] = g_x[idx] + g_xp[(long)p * C_ + c] - g_xp0[(long)p * C_ + c];
    }
}

#define GETSYM(p, var) cudaGetSymbolAddress((void**)&(p), var)

static inline int smem_bytes(bool bt, int bn) {
    int sa = 128 * 36;
    int sb = bt ? bn * 36 : 32 * (bn + 8);
    return 3 * (sa + sb) * 4;
}

extern "C" void kernel_launch(void* const* d_in, const int* in_sizes, int n_in,
                              void* d_out, int out_size)
{
    const float* feats   = (const float*)d_in[0];
    const float* mod     = (const float*)d_in[1];
    const float* context = (const float*)d_in[2];
    const float* Wq  = (const float*)d_in[3];
    const float* bq  = (const float*)d_in[4];
    const float* Wkv = (const float*)d_in[5];
    const float* bkv = (const float*)d_in[6];
    const float* Wo  = (const float*)d_in[7];
    const float* bo  = (const float*)d_in[8];
    const float* qg  = (const float*)d_in[9];
    const float* kg  = (const float*)d_in[10];
    const float* Wcq = (const float*)d_in[11];
    const float* bcq = (const float*)d_in[12];
    const float* Wckv= (const float*)d_in[13];
    const float* bckv= (const float*)d_in[14];
    const float* Wco = (const float*)d_in[15];
    const float* bco = (const float*)d_in[16];
    const float* W12 = (const float*)d_in[17];
    const float* b12 = (const float*)d_in[18];
    const float* W3  = (const float*)d_in[19];
    const float* b3  = (const float*)d_in[20];
    const float* Wm  = (const float*)d_in[21];
    const float* bm  = (const float*)d_in[22];
    const int* coords  = (const int*)d_in[23];
    const int* inverse = (const int*)d_in[24];
    const int* pcoords = (const int*)d_in[25];
    float* out = (float*)d_out;

    float *p_m, *p_h, *p_q, *p_o, *p_x, *p_S, *p_hp, *p_kv, *p_xp0, *p_xp,
          *p_hp2, *p_cq, *p_ckv, *p_S2, *p_co, *p_ab, *p_gact;
    int* p_cnt;
    GETSYM(p_m, g_m);   GETSYM(p_h, g_h);   GETSYM(p_q, g_q);   GETSYM(p_o, g_o);
    GETSYM(p_x, g_x);   GETSYM(p_S, g_S);   GETSYM(p_hp, g_hp); GETSYM(p_kv, g_kv);
    GETSYM(p_xp0, g_xp0); GETSYM(p_xp, g_xp); GETSYM(p_hp2, g_hp2);
    GETSYM(p_cq, g_cq); GETSYM(p_ckv, g_ckv); GETSYM(p_S2, g_S2); GETSYM(p_co, g_co);
    GETSYM(p_ab, g_ab); GETSYM(p_gact, g_gact); GETSYM(p_cnt, g_cnt);

    const int smNN  = smem_bytes(false, 128);
    const int smBT  = smem_bytes(true, 128);
    const int smNN64= smem_bytes(false, 64);
    cudaFuncSetAttribute((const void*)gemm_tc<false, 0, 128>,
                         cudaFuncAttributeMaxDynamicSharedMemorySize, smNN);
    cudaFuncSetAttribute((const void*)gemm_tc<false, 1, 128>,
                         cudaFuncAttributeMaxDynamicSharedMemorySize, smNN);
    cudaFuncSetAttribute((const void*)gemm_tc<true, 0, 128>,
                         cudaFuncAttributeMaxDynamicSharedMemorySize, smBT);
    cudaFuncSetAttribute((const void*)gemm_tc<false, 0, 64>,
                         cudaFuncAttributeMaxDynamicSharedMemorySize, smNN64);

    modproj_kernel<<<(NM_ + 255) / 256, 256>>>(mod, Wm, bm);

    cudaMemsetAsync(p_cnt, 0, P_ * sizeof(int));
    build_members_kernel<<<T_ / 256, 256>>>(inverse);
    sort_members_kernel<<<2, 256>>>();

    ln_mod_kernel<<<T_, 256>>>(feats, p_h, p_m + C_, p_m);

    // q = h @ Wq + bq
    gemm_tc<false, 0, 128><<<dim3(C_ / 128, T_ / 128, 1), 256, smNN>>>(
        T_, C_, C_, p_h, C_, 0, Wq, C_, 1, 0, p_q, C_, 0, bq, nullptr, 0, nullptr);

    seg_mean_kernel<<<P_, 256>>>(p_h, p_hp, nullptr);
    gemm_tc<false, 0, 128><<<dim3(2 * C_ / 128, P_ / 128, 1), 256, smNN>>>(
        P_, 2 * C_, C_, p_hp, C_, 0, Wkv, 2 * C_, 1, 0, p_kv, 2 * C_, 0, bkv,
        nullptr, 0, nullptr);

    rope_norm_kernel<<<(T_ * H_ * 32) / 256, 256>>>(p_q, C_, T_, coords, 1, qg);
    rope_norm_kernel<<<(P_ * H_ * 32) / 256, 256>>>(p_kv, 2 * C_, P_, pcoords, 4, kg);

    // S[h] = Q_h @ K_h^T
    gemm_tc<true, 0, 128><<<dim3(P_ / 128, T_ / 128, H_), 256, smBT>>>(
        T_, P_, D_, p_q, C_, 64, p_kv, 1, 2 * C_, 64,
        p_S, P_, (long)T_ * P_, nullptr, nullptr, 0, nullptr);
    softmax_kernel<16><<<(H_ * T_) / 8, 256>>>(p_S, (long)H_ * T_, 0.125f);

    // O[h] = S_h @ V_h
    gemm_tc<false, 0, 64><<<dim3(1, T_ / 128, H_), 256, smNN64>>>(
        T_, D_, P_, p_S, P_, (long)T_ * P_, p_kv + C_, 2 * C_, 1, 64,
        p_o, C_, 64, nullptr, nullptr, 0, nullptr);

    // x = feats + (o @ Wo + bo) * g_msa
    gemm_tc<false, 1, 128><<<dim3(C_ / 128, T_ / 128, 1), 256, smNN>>>(
        T_, C_, C_, p_o, C_, 0, Wo, C_, 1, 0, p_x, C_, 0, bo, feats, C_, p_m + 2 * C_);

    seg_mean_kernel<<<P_, 256>>>(p_x, p_xp0, p_xp);
    ln_mod_kernel<<<P_, 256>>>(p_xp, p_hp2, p_m + 4 * C_, p_m + 3 * C_);
    gemm_tc<false, 0, 128><<<dim3(C_ / 128, P_ / 128, 1), 256, smNN>>>(
        P_, C_, C_, p_hp2, C_, 0, Wcq, C_, 1, 0, p_cq, C_, 0, bcq, nullptr, 0, nullptr);
    gemm_tc<false, 0, 128><<<dim3(2 * C_ / 128, L_ / 128, 1), 256, smNN>>>(
        L_, 2 * C_, C_, context, C_, 0, Wckv, 2 * C_, 1, 0, p_ckv, 2 * C_, 0, bckv,
        nullptr, 0, nullptr);

    gemm_tc<true, 0, 128><<<dim3(L_ / 128, P_ / 128, H_), 256, smBT>>>(
        P_, L_, D_, p_cq, C_, 64, p_ckv, 1, 2 * C_, 64,
        p_S2, L_, (long)P_ * L_, nullptr, nullptr, 0, nullptr);
    softmax_kernel<32><<<(H_ * P_) / 8, 256>>>(p_S2, (long)H_ * P_, 0.125f);
    gemm_tc<false, 0, 64><<<dim3(1, P_ / 128, H_), 256, smNN64>>>(
        P_, D_, L_, p_S2, L_, (long)P_ * L_, p_ckv + C_, 2 * C_, 1, 64,
        p_co, C_, 64, nullptr, nullptr, 0, nullptr);

    gemm_tc<false, 1, 128><<<dim3(C_ / 128, P_ / 128, 1), 256, smNN>>>(
        P_, C_, C_, p_co, C_, 0, Wco, C_, 1, 0, p_xp, C_, 0, bco, p_xp, C_,
        p_m + 5 * C_);

    ln_mod_kernel<<<P_, 256>>>(p_xp, p_hp2, p_m + 7 * C_, p_m + 6 * C_);
    gemm_tc<false, 0, 128><<<dim3(2 * HID_ / 128, P_ / 128, 1), 256, smNN>>>(
        P_, 2 * HID_, C_, p_hp2, C_, 0, W12, 2 * HID_, 1, 0, p_ab, 2 * HID_, 0, b12,
        nullptr, 0, nullptr);
    silugate_kernel<<<(P_ * HID_) / 256, 256>>>();
    gemm_tc<false, 1, 128><<<dim3(C_ / 128, P_ / 128, 1), 256, smNN>>>(
        P_, C_, HID_, p_gact, HID_, 0, W3, C_, 1, 0, p_xp, C_, 0, b3, p_xp, C_,
        p_m + 8 * C_);

    final_kernel<<<((long)T_ * C_) / 256, 256>>>(inverse, out);
}

// round 4
// speedup vs baseline: 4.0352x; 1.1485x over previous
#include <cuda_runtime.h>
#include <cuda_bf16.h>
#include <math.h>
#include <stdint.h>

#define T_   16384
#define C_   1024
#define H_   16
#define D_   64
#define P_   512
#define L_   1024
#define HID_ 4096
#define NM_  9216

__device__ float g_m[NM_];
__device__ float g_h[(size_t)T_ * C_];
__device__ float g_q[(size_t)T_ * C_];
__device__ float g_o[(size_t)T_ * C_];
__device__ float g_x[(size_t)T_ * C_];
__device__ float g_hp[(size_t)P_ * C_];
__device__ float g_kv[(size_t)P_ * 2 * C_];
__device__ float g_xp0[(size_t)P_ * C_];
__device__ float g_xp[(size_t)P_ * C_];
__device__ float g_hp2[(size_t)P_ * C_];
__device__ float g_cq[(size_t)P_ * C_];
__device__ float g_ckv[(size_t)L_ * 2 * C_];
__device__ float g_co[(size_t)P_ * C_];
__device__ float g_ab[(size_t)P_ * 2 * HID_];
__device__ float g_gact[(size_t)P_ * HID_];
__device__ int   g_cnt[P_];
__device__ int   g_members[P_ * 64];

__device__ __forceinline__ void cp16(uint32_t s, const float* g) {
    asm volatile("cp.async.ca.shared.global [%0], [%1], 16;\n" :: "r"(s), "l"(g));
}
__device__ __forceinline__ void cp_commit() {
    asm volatile("cp.async.commit_group;\n");
}
template<int N>
__device__ __forceinline__ void cp_wait() {
    asm volatile("cp.async.wait_group %0;\n" :: "n"(N));
}

__device__ __forceinline__ void mma_tf32(float* c, const uint32_t* a, const uint32_t* b) {
    asm volatile(
        "mma.sync.aligned.m16n8k8.row.col.f32.tf32.tf32.f32 "
        "{%0,%1,%2,%3}, {%4,%5,%6,%7}, {%8,%9}, {%0,%1,%2,%3};\n"
        : "+f"(c[0]), "+f"(c[1]), "+f"(c[2]), "+f"(c[3])
        : "r"(a[0]), "r"(a[1]), "r"(a[2]), "r"(a[3]), "r"(b[0]), "r"(b[1]));
}

// ======================= flash attention (tf32) =======================
// O[m][d] = softmax_n( Q[m][:]·K[n][:] * 0.125 ) @ V[n][d]
// Q rows at Qp + m*qStride + h*64.  K rows at KVp + n*kvStride + h*64,
// V rows at KVp + n*kvStride + vOff + h*64.  Out rows Op + m*oStride + h*64.
// M % 128 == 0, NKV % 64 == 0.
#define KS_FL 4352   // 64*68
#define VS_FL 4608   // 64*72
#define PS_OFF 17920 // 2*KS_FL + 2*VS_FL
#define FL_SMEM_BYTES ((PS_OFF + 8 * 16 * 68) * 4)   // 106496

__global__ __launch_bounds__(256)
void flash_attn(const float* __restrict__ Qp, int qStride,
                const float* __restrict__ KVp, int kvStride, long vOff,
                float* __restrict__ Op, int oStride, int NKV)
{
    extern __shared__ float sm_[];
    const int h = blockIdx.y;
    const int hbase = h * D_;
    const int row0 = blockIdx.x * 128;
    const int tid = threadIdx.x;
    const int lane = tid & 31;
    const int wid = tid >> 5;
    const int lr = lane >> 2, lc = lane & 3;

    const uint32_t smemBase = (uint32_t)__cvta_generic_to_shared(sm_);

    auto loadKV = [&](int stage, int kv0) {
#pragma unroll
        for (int p = 0; p < 4; p++) {
            int sl = tid + p * 256;
            int r = sl >> 4, qd = sl & 15;
            const float* krow = KVp + (long)(kv0 + r) * kvStride + hbase + qd * 4;
            cp16(smemBase + (uint32_t)(stage * KS_FL + r * 68 + qd * 4) * 4u, krow);
            cp16(smemBase + (uint32_t)(2 * KS_FL + stage * VS_FL + r * 72 + qd * 4) * 4u,
                 krow + vOff);
        }
    };

    // prologue: stage 0 + Q fragment preload (overlapped)
    loadKV(0, 0);
    cp_commit();

    uint32_t qa[8][4];
    {
        const float* Qb = Qp + (long)(row0 + wid * 16) * qStride + hbase;
#pragma unroll
        for (int kk = 0; kk < 8; kk++) {
            qa[kk][0] = __float_as_uint(Qb[(long)lr * qStride + kk * 8 + lc]);
            qa[kk][1] = __float_as_uint(Qb[(long)(lr + 8) * qStride + kk * 8 + lc]);
            qa[kk][2] = __float_as_uint(Qb[(long)lr * qStride + kk * 8 + lc + 4]);
            qa[kk][3] = __float_as_uint(Qb[(long)(lr + 8) * qStride + kk * 8 + lc + 4]);
        }
    }

    float oacc[8][4];
#pragma unroll
    for (int i = 0; i < 8; i++)
#pragma unroll
        for (int j = 0; j < 4; j++) oacc[i][j] = 0.f;
    float m0 = -INFINITY, m1 = -INFINITY, l0 = 0.f, l1 = 0.f;

    float* Pw = sm_ + PS_OFF + wid * 16 * 68;
    const int nkt = NKV / 64;

    for (int it = 0; it < nkt; it++) {
        cp_wait<0>();
        __syncthreads();
        if (it + 1 < nkt) loadKV((it + 1) & 1, (it + 1) * 64);
        cp_commit();

        const int st = it & 1;
        const float* Kst = sm_ + st * KS_FL;
        const float* Vst = sm_ + 2 * KS_FL + st * VS_FL;

        // ---- S = Q @ K^T ----
        float sacc[8][4];
#pragma unroll
        for (int i = 0; i < 8; i++)
#pragma unroll
            for (int j = 0; j < 4; j++) sacc[i][j] = 0.f;

#pragma unroll
        for (int kk = 0; kk < 8; kk++) {
            uint32_t b[8][2];
#pragma unroll
            for (int ni = 0; ni < 8; ni++) {
                b[ni][0] = __float_as_uint(Kst[(ni * 8 + lr) * 68 + kk * 8 + lc]);
                b[ni][1] = __float_as_uint(Kst[(ni * 8 + lr) * 68 + kk * 8 + lc + 4]);
            }
#pragma unroll
            for (int ni = 0; ni < 8; ni++)
                mma_tf32(sacc[ni], qa[kk], b[ni]);
        }

        // ---- online softmax ----
        float mx0 = m0, mx1 = m1;
#pragma unroll
        for (int ni = 0; ni < 8; ni++) {
#pragma unroll
            for (int j = 0; j < 4; j++) sacc[ni][j] *= 0.125f;
            mx0 = fmaxf(mx0, fmaxf(sacc[ni][0], sacc[ni][1]));
            mx1 = fmaxf(mx1, fmaxf(sacc[ni][2], sacc[ni][3]));
        }
#pragma unroll
        for (int o = 1; o <= 2; o <<= 1) {
            mx0 = fmaxf(mx0, __shfl_xor_sync(0xffffffffu, mx0, o));
            mx1 = fmaxf(mx1, __shfl_xor_sync(0xffffffffu, mx1, o));
        }
        float al0 = __expf(m0 - mx0), al1 = __expf(m1 - mx1);
        float s0 = 0.f, s1 = 0.f;
#pragma unroll
        for (int ni = 0; ni < 8; ni++) {
            sacc[ni][0] = __expf(sacc[ni][0] - mx0);
            sacc[ni][1] = __expf(sacc[ni][1] - mx0);
            sacc[ni][2] = __expf(sacc[ni][2] - mx1);
            sacc[ni][3] = __expf(sacc[ni][3] - mx1);
            s0 += sacc[ni][0] + sacc[ni][1];
            s1 += sacc[ni][2] + sacc[ni][3];
        }
#pragma unroll
        for (int o = 1; o <= 2; o <<= 1) {
            s0 += __shfl_xor_sync(0xffffffffu, s0, o);
            s1 += __shfl_xor_sync(0xffffffffu, s1, o);
        }
        l0 = l0 * al0 + s0;
        l1 = l1 * al1 + s1;
        m0 = mx0; m1 = mx1;
#pragma unroll
        for (int ni = 0; ni < 8; ni++) {
            oacc[ni][0] *= al0; oacc[ni][1] *= al0;
            oacc[ni][2] *= al1; oacc[ni][3] *= al1;
        }

        // ---- stage P (per-warp) ----
        __syncwarp();
#pragma unroll
        for (int ni = 0; ni < 8; ni++) {
            *reinterpret_cast<float2*>(&Pw[lr * 68 + ni * 8 + 2 * lc]) =
                make_float2(sacc[ni][0], sacc[ni][1]);
            *reinterpret_cast<float2*>(&Pw[(lr + 8) * 68 + ni * 8 + 2 * lc]) =
                make_float2(sacc[ni][2], sacc[ni][3]);
        }
        __syncwarp();

        // ---- O += P @ V ----
#pragma unroll
        for (int kk = 0; kk < 8; kk++) {
            uint32_t a[4];
            a[0] = __float_as_uint(Pw[lr * 68 + kk * 8 + lc]);
            a[1] = __float_as_uint(Pw[(lr + 8) * 68 + kk * 8 + lc]);
            a[2] = __float_as_uint(Pw[lr * 68 + kk * 8 + lc + 4]);
            a[3] = __float_as_uint(Pw[(lr + 8) * 68 + kk * 8 + lc + 4]);
#pragma unroll
            for (int ni = 0; ni < 8; ni++) {
                uint32_t b[2];
                b[0] = __float_as_uint(Vst[(kk * 8 + lc) * 72 + ni * 8 + lr]);
                b[1] = __float_as_uint(Vst[(kk * 8 + lc + 4) * 72 + ni * 8 + lr]);
                mma_tf32(oacc[ni], a, b);
            }
        }
    }

    // ---- epilogue ----
    float il0 = 1.f / l0, il1 = 1.f / l1;
    const int t0 = row0 + wid * 16 + lr;
#pragma unroll
    for (int ni = 0; ni < 8; ni++) {
        *reinterpret_cast<float2*>(Op + (long)t0 * oStride + hbase + ni * 8 + 2 * lc) =
            make_float2(oacc[ni][0] * il0, oacc[ni][1] * il0);
        *reinterpret_cast<float2*>(Op + (long)(t0 + 8) * oStride + hbase + ni * 8 + 2 * lc) =
            make_float2(oacc[ni][2] * il1, oacc[ni][3] * il1);
    }
}

// ======================= pipelined GEMM (tf32) =======================
template<bool BT, int EPI, int BN>
__global__ __launch_bounds__(256)
void gemm_tc(int M, int N, int K,
             const float* __restrict__ A, int lda, long aB,
             const float* __restrict__ B, int bKs, int bNs, long bB,
             float* __restrict__ Cp, int ldc, long cB,
             const float* __restrict__ bias,
             const float* __restrict__ resid, int ldr,
             const float* __restrict__ gate)
{
    constexpr int BM = 128, BK = 32, STAGES = 3;
    constexpr int LDA = BK + 4;
    constexpr int SB  = BT ? (BN * LDA) : (BK * (BN + 8));
    constexpr int SA  = BM * LDA;
    extern __shared__ float sm_[];
    float* As = sm_;
    float* Bs = sm_ + STAGES * SA;

    const int bz = blockIdx.z;
    const float* Ab = A + (long)bz * aB;
    const float* Bb = B + (long)bz * bB;
    float*       Cb = Cp + (long)bz * cB;
    const int row0 = blockIdx.y * BM;
    const int col0 = blockIdx.x * BN;
    const int tid  = threadIdx.x;
    const int lane = tid & 31;
    const int wid  = tid >> 5;
    const int lr = lane >> 2, lc = lane & 3;

    constexpr int MI = (BN == 128) ? 4 : 2;
    constexpr int NI = 4;
    int warpM, warpN;
    if (BN == 128) { warpM = (wid & 1) * 64; warpN = (wid >> 1) * 32; }
    else           { warpM = (wid & 3) * 32; warpN = (wid >> 2) * 32; }

    float acc[MI][NI][4];
#pragma unroll
    for (int i = 0; i < MI; i++)
#pragma unroll
        for (int j = 0; j < NI; j++)
#pragma unroll
            for (int r = 0; r < 4; r++) acc[i][j][r] = 0.f;

    const int aq = tid & 7;
    const int am = tid >> 3;
    const uint32_t smemA0 = (uint32_t)__cvta_generic_to_shared(As);
    const uint32_t smemB0 = (uint32_t)__cvta_generic_to_shared(Bs);

    auto loadA = [&](int stage, int k0) {
        uint32_t base = smemA0 + (uint32_t)(stage * SA) * 4u;
#pragma unroll
        for (int i = 0; i < 4; i++) {
            int m = am + 32 * i;
            cp16(base + (uint32_t)(m * LDA + aq * 4) * 4u,
                 Ab + (long)(row0 + m) * lda + k0 + aq * 4);
        }
    };
    auto loadB = [&](int stage, int k0) {
        uint32_t base = smemB0 + (uint32_t)(stage * SB) * 4u;
        if (BT) {
#pragma unroll
            for (int i = 0; i < BN / 32; i++) {
                int n = am + 32 * i;
                cp16(base + (uint32_t)(n * LDA + aq * 4) * 4u,
                     Bb + (long)(col0 + n) * bNs + k0 + aq * 4);
            }
        } else if (BN == 128) {
            int nq = tid & 31, bk = tid >> 5;
#pragma unroll
            for (int i = 0; i < 4; i++) {
                int kk = bk + 8 * i;
                cp16(base + (uint32_t)(kk * (BN + 8) + nq * 4) * 4u,
                     Bb + (long)(k0 + kk) * bKs + col0 + nq * 4);
            }
        } else {
            int nq = tid & 15, bk = tid >> 4;
#pragma unroll
            for (int i = 0; i < 2; i++) {
                int kk = bk + 16 * i;
                cp16(base + (uint32_t)(kk * (BN + 8) + nq * 4) * 4u,
                     Bb + (long)(k0 + kk) * bKs + col0 + nq * 4);
            }
        }
    };

    const int nkt = K / BK;
#pragma unroll
    for (int s = 0; s < STAGES - 1; s++) {
        if (s < nkt) { loadA(s, s * BK); loadB(s, s * BK); }
        cp_commit();
    }

    for (int kt = 0; kt < nkt; kt++) {
        cp_wait<STAGES - 2>();
        __syncthreads();
        int kn = kt + STAGES - 1;
        if (kn < nkt) { loadA(kn % STAGES, kn * BK); loadB(kn % STAGES, kn * BK); }
        cp_commit();

        const float* Asb = As + (kt % STAGES) * SA;
        const float* Bsb = Bs + (kt % STAGES) * SB;
#pragma unroll
        for (int kk = 0; kk < 4; kk++) {
            uint32_t a[MI][4], b[NI][2];
#pragma unroll
            for (int mi = 0; mi < MI; mi++) {
                int m = warpM + mi * 16 + lr;
                a[mi][0] = __float_as_uint(Asb[m * LDA + kk * 8 + lc]);
                a[mi][1] = __float_as_uint(Asb[(m + 8) * LDA + kk * 8 + lc]);
                a[mi][2] = __float_as_uint(Asb[m * LDA + kk * 8 + lc + 4]);
                a[mi][3] = __float_as_uint(Asb[(m + 8) * LDA + kk * 8 + lc + 4]);
            }
#pragma unroll
            for (int ni = 0; ni < NI; ni++) {
                int n = warpN + ni * 8 + lr;
                if (BT) {
                    b[ni][0] = __float_as_uint(Bsb[n * LDA + kk * 8 + lc]);
                    b[ni][1] = __float_as_uint(Bsb[n * LDA + kk * 8 + lc + 4]);
                } else {
                    b[ni][0] = __float_as_uint(Bsb[(kk * 8 + lc) * (BN + 8) + n]);
                    b[ni][1] = __float_as_uint(Bsb[(kk * 8 + lc + 4) * (BN + 8) + n]);
                }
            }
#pragma unroll
            for (int mi = 0; mi < MI; mi++)
#pragma unroll
                for (int ni = 0; ni < NI; ni++)
                    mma_tf32(acc[mi][ni], a[mi], b[ni]);
        }
        __syncthreads();
    }

#pragma unroll
    for (int mi = 0; mi < MI; mi++) {
#pragma unroll
        for (int ni = 0; ni < NI; ni++) {
            int gm0 = row0 + warpM + mi * 16 + lr;
            int gn  = col0 + warpN + ni * 8 + lc * 2;
#pragma unroll
            for (int half = 0; half < 2; half++) {
                int gm = gm0 + half * 8;
                float v0 = acc[mi][ni][half * 2 + 0];
                float v1 = acc[mi][ni][half * 2 + 1];
                if (bias) { v0 += bias[gn]; v1 += bias[gn + 1]; }
                if (EPI == 1) {
                    const float2 rr = *reinterpret_cast<const float2*>(
                        resid + (long)gm * ldr + gn);
                    v0 = rr.x + v0 * gate[gn];
                    v1 = rr.y + v1 * gate[gn + 1];
                }
                *reinterpret_cast<float2*>(Cb + (long)gm * ldc + gn) =
                    make_float2(v0, v1);
            }
        }
    }
}

__global__ void modproj_kernel(const float* __restrict__ mod,
                               const float* __restrict__ Wm,
                               const float* __restrict__ bm)
{
    __shared__ float sm[C_];
    for (int i = threadIdx.x; i < C_; i += blockDim.x) {
        float v = mod[i];
        sm[i] = v / (1.f + expf(-v));
    }
    __syncthreads();
    int j = blockIdx.x * blockDim.x + threadIdx.x;
    if (j < NM_) {
        float acc = bm[j];
        for (int i = 0; i < C_; i++) acc += sm[i] * Wm[(long)i * NM_ + j];
        g_m[j] = acc;
    }
}

__global__ void ln_mod_kernel(const float* __restrict__ in, float* __restrict__ out,
                              const float* __restrict__ sc, const float* __restrict__ sh)
{
    __shared__ float rs[256], rs2[256];
    int r = blockIdx.x, tid = threadIdx.x;
    const float* x = in + (long)r * C_;
    float v[4], s = 0.f, s2 = 0.f;
#pragma unroll
    for (int i = 0; i < 4; i++) { v[i] = x[tid + i * 256]; s += v[i]; s2 += v[i] * v[i]; }
    rs[tid] = s; rs2[tid] = s2; __syncthreads();
    for (int o = 128; o; o >>= 1) {
        if (tid < o) { rs[tid] += rs[tid + o]; rs2[tid] += rs2[tid + o]; }
        __syncthreads();
    }
    float mu = rs[0] * (1.f / C_);
    float var = rs2[0] * (1.f / C_) - mu * mu;
    float rstd = rsqrtf(fmaxf(var, 0.f) + 1e-6f);
#pragma unroll
    for (int i = 0; i < 4; i++) {
        int c = tid + i * 256;
        out[(long)r * C_ + c] = (v[i] - mu) * rstd * (1.f + sc[c]) + sh[c];
    }
}

__global__ void build_members_kernel(const int* __restrict__ inv)
{
    int t = blockIdx.x * blockDim.x + threadIdx.x;
    if (t < T_) {
        int p = inv[t];
        int s = atomicAdd(&g_cnt[p], 1);
        if (s < 64) g_members[p * 64 + s] = t;
    }
}

__global__ void sort_members_kernel()
{
    int p = blockIdx.x * blockDim.x + threadIdx.x;
    if (p < P_) {
        int n = min(g_cnt[p], 64);
        int* a = &g_members[p * 64];
        for (int i = 1; i < n; i++) {
            int key = a[i], j = i - 1;
            while (j >= 0 && a[j] > key) { a[j + 1] = a[j]; --j; }
            a[j + 1] = key;
        }
    }
}

__global__ void seg_mean_kernel(const float* __restrict__ in, float* __restrict__ out,
                                float* __restrict__ out2)
{
    int p = blockIdx.x, tid = threadIdx.x;
    int n = min(g_cnt[p], 64);
    float acc[4] = {0.f, 0.f, 0.f, 0.f};
    for (int j = 0; j < n; j++) {
        long base = (long)g_members[p * 64 + j] * C_;
#pragma unroll
        for (int i = 0; i < 4; i++) acc[i] += in[base + tid + i * 256];
    }
    float invn = n ? 1.f / n : 0.f;
#pragma unroll
    for (int i = 0; i < 4; i++) {
        float val = acc[i] * invn;
        out[(long)p * C_ + tid + i * 256] = val;
        if (out2) out2[(long)p * C_ + tid + i * 256] = val;
    }
}

__global__ void rope_norm_kernel(float* __restrict__ x, int rowStride, int rows,
                                 const int* __restrict__ coords, int cmult,
                                 const float* __restrict__ gamma)
{
    long gw = ((long)blockIdx.x * blockDim.x + threadIdx.x) >> 5;
    if (gw >= (long)rows * H_) return;
    int lane = threadIdx.x & 31;
    int t = (int)(gw / H_), h = (int)(gw % H_);
    float* base = x + (long)t * rowStride + h * D_;
    float x0 = base[2 * lane], x1 = base[2 * lane + 1];
    float c = 1.f, s = 0.f;
    if (lane < 30) {
        int a = lane / 10, f = lane % 10;
        float freq = powf(10000.f, -(float)f * 0.1f);
        float ang = (float)(coords[t * 3 + a] * cmult) * freq;
        c = cosf(ang); s = sinf(ang);
    }
    float re = x0 * c - x1 * s;
    float im = x0 * s + x1 * c;
    float ss = re * re + im * im;
#pragma unroll
    for (int o = 16; o; o >>= 1) ss += __shfl_xor_sync(0xffffffffu, ss, o);
    float nrm = sqrtf(ss);
    float scl = 8.f / fmaxf(nrm, 1e-12f);
    base[2 * lane]     = re * scl * gamma[h * D_ + 2 * lane];
    base[2 * lane + 1] = im * scl * gamma[h * D_ + 2 * lane + 1];
}

__global__ void silugate_kernel()
{
    long idx = (long)blockIdx.x * blockDim.x + threadIdx.x;
    if (idx < (long)P_ * HID_) {
        int p = (int)(idx >> 12), i = (int)(idx & (HID_ - 1));
        float a = g_ab[(long)p * 2 * HID_ + i];
        float b = g_ab[(long)p * 2 * HID_ + HID_ + i];
        g_gact[idx] = a / (1.f + expf(-a)) * b;
    }
}

__global__ void final_kernel(const int* __restrict__ inv, float* __restrict__ out)
{
    long idx = (long)blockIdx.x * blockDim.x + threadIdx.x;
    if (idx < (long)T_ * C_) {
        int t = (int)(idx >> 10), c = (int)(idx & (C_ - 1));
        int p = inv[t];
        out[idx] = g_x[idx] + g_xp[(long)p * C_ + c] - g_xp0[(long)p * C_ + c];
    }
}

#define GETSYM(p, var) cudaGetSymbolAddress((void**)&(p), var)

static inline int smem_bytes(bool bt, int bn) {
    int sa = 128 * 36;
    int sb = bt ? bn * 36 : 32 * (bn + 8);
    return 3 * (sa + sb) * 4;
}

extern "C" void kernel_launch(void* const* d_in, const int* in_sizes, int n_in,
                              void* d_out, int out_size)
{
    const float* feats   = (const float*)d_in[0];
    const float* mod     = (const float*)d_in[1];
    const float* context = (const float*)d_in[2];
    const float* Wq  = (const float*)d_in[3];
    const float* bq  = (const float*)d_in[4];
    const float* Wkv = (const float*)d_in[5];
    const float* bkv = (const float*)d_in[6];
    const float* Wo  = (const float*)d_in[7];
    const float* bo  = (const float*)d_in[8];
    const float* qg  = (const float*)d_in[9];
    const float* kg  = (const float*)d_in[10];
    const float* Wcq = (const float*)d_in[11];
    const float* bcq = (const float*)d_in[12];
    const float* Wckv= (const float*)d_in[13];
    const float* bckv= (const float*)d_in[14];
    const float* Wco = (const float*)d_in[15];
    const float* bco = (const float*)d_in[16];
    const float* W12 = (const float*)d_in[17];
    const float* b12 = (const float*)d_in[18];
    const float* W3  = (const float*)d_in[19];
    const float* b3  = (const float*)d_in[20];
    const float* Wm  = (const float*)d_in[21];
    const float* bm  = (const float*)d_in[22];
    const int* coords  = (const int*)d_in[23];
    const int* inverse = (const int*)d_in[24];
    const int* pcoords = (const int*)d_in[25];
    float* out = (float*)d_out;

    float *p_m, *p_h, *p_q, *p_o, *p_x, *p_hp, *p_kv, *p_xp0, *p_xp,
          *p_hp2, *p_cq, *p_ckv, *p_co, *p_ab, *p_gact;
    int* p_cnt;
    GETSYM(p_m, g_m);   GETSYM(p_h, g_h);   GETSYM(p_q, g_q);   GETSYM(p_o, g_o);
    GETSYM(p_x, g_x);   GETSYM(p_hp, g_hp); GETSYM(p_kv, g_kv);
    GETSYM(p_xp0, g_xp0); GETSYM(p_xp, g_xp); GETSYM(p_hp2, g_hp2);
    GETSYM(p_cq, g_cq); GETSYM(p_ckv, g_ckv); GETSYM(p_co, g_co);
    GETSYM(p_ab, g_ab); GETSYM(p_gact, g_gact); GETSYM(p_cnt, g_cnt);

    const int smNN   = smem_bytes(false, 128);
    cudaFuncSetAttribute((const void*)gemm_tc<false, 0, 128>,
                         cudaFuncAttributeMaxDynamicSharedMemorySize, smNN);
    cudaFuncSetAttribute((const void*)gemm_tc<false, 1, 128>,
                         cudaFuncAttributeMaxDynamicSharedMemorySize, smNN);
    cudaFuncSetAttribute((const void*)flash_attn,
                         cudaFuncAttributeMaxDynamicSharedMemorySize, FL_SMEM_BYTES);

    modproj_kernel<<<(NM_ + 255) / 256, 256>>>(mod, Wm, bm);

    cudaMemsetAsync(p_cnt, 0, P_ * sizeof(int));
    build_members_kernel<<<T_ / 256, 256>>>(inverse);
    sort_members_kernel<<<2, 256>>>();

    ln_mod_kernel<<<T_, 256>>>(feats, p_h, p_m + C_, p_m);

    // q = h @ Wq + bq
    gemm_tc<false, 0, 128><<<dim3(C_ / 128, T_ / 128, 1), 256, smNN>>>(
        T_, C_, C_, p_h, C_, 0, Wq, C_, 1, 0, p_q, C_, 0, bq, nullptr, 0, nullptr);

    seg_mean_kernel<<<P_, 256>>>(p_h, p_hp, nullptr);
    gemm_tc<false, 0, 128><<<dim3(2 * C_ / 128, P_ / 128, 1), 256, smNN>>>(
        P_, 2 * C_, C_, p_hp, C_, 0, Wkv, 2 * C_, 1, 0, p_kv, 2 * C_, 0, bkv,
        nullptr, 0, nullptr);

    rope_norm_kernel<<<(T_ * H_ * 32) / 256, 256>>>(p_q, C_, T_, coords, 1, qg);
    rope_norm_kernel<<<(P_ * H_ * 32) / 256, 256>>>(p_kv, 2 * C_, P_, pcoords, 4, kg);

    // fused self-attention: o = softmax(q k^T / 8) v
    flash_attn<<<dim3(T_ / 128, H_), 256, FL_SMEM_BYTES>>>(
        p_q, C_, p_kv, 2 * C_, C_, p_o, C_, P_);

    // x = feats + (o @ Wo + bo) * g_msa
    gemm_tc<false, 1, 128><<<dim3(C_ / 128, T_ / 128, 1), 256, smNN>>>(
        T_, C_, C_, p_o, C_, 0, Wo, C_, 1, 0, p_x, C_, 0, bo, feats, C_, p_m + 2 * C_);

    seg_mean_kernel<<<P_, 256>>>(p_x, p_xp0, p_xp);
    ln_mod_kernel<<<P_, 256>>>(p_xp, p_hp2, p_m + 4 * C_, p_m + 3 * C_);
    gemm_tc<false, 0, 128><<<dim3(C_ / 128, P_ / 128, 1), 256, smNN>>>(
        P_, C_, C_, p_hp2, C_, 0, Wcq, C_, 1, 0, p_cq, C_, 0, bcq, nullptr, 0, nullptr);
    gemm_tc<false, 0, 128><<<dim3(2 * C_ / 128, L_ / 128, 1), 256, smNN>>>(
        L_, 2 * C_, C_, context, C_, 0, Wckv, 2 * C_, 1, 0, p_ckv, 2 * C_, 0, bckv,
        nullptr, 0, nullptr);

    // fused cross-attention
    flash_attn<<<dim3(P_ / 128, H_), 256, FL_SMEM_BYTES>>>(
        p_cq, C_, p_ckv, 2 * C_, C_, p_co, C_, L_);

    gemm_tc<false, 1, 128><<<dim3(C_ / 128, P_ / 128, 1), 256, smNN>>>(
        P_, C_, C_, p_co, C_, 0, Wco, C_, 1, 0, p_xp, C_, 0, bco, p_xp, C_,
        p_m + 5 * C_);

    ln_mod_kernel<<<P_, 256>>>(p_xp, p_hp2, p_m + 7 * C_, p_m + 6 * C_);
    gemm_tc<false, 0, 128><<<dim3(2 * HID_ / 128, P_ / 128, 1), 256, smNN>>>(
        P_, 2 * HID_, C_, p_hp2, C_, 0, W12, 2 * HID_, 1, 0, p_ab, 2 * HID_, 0, b12,
        nullptr, 0, nullptr);
    silugate_kernel<<<(P_ * HID_) / 256, 256>>>();
    gemm_tc<false, 1, 128><<<dim3(C_ / 128, P_ / 128, 1), 256, smNN>>>(
        P_, C_, HID_, p_gact, HID_, 0, W3, C_, 1, 0, p_xp, C_, 0, b3, p_xp, C_,
        p_m + 8 * C_);

    final_kernel<<<((long)T_ * C_) / 256, 256>>>(inverse, out);
}